// round 1
// baseline (speedup 1.0000x reference)
#include <cuda_runtime.h>
#include <cstddef>
#include <cstdint>

// Problem shape (fixed by the benchmark)
constexpr int B_ = 16;
constexpr int N_ = 2048;
constexpr int D_ = 64;
constexpr size_t N2 = (size_t)N_ * N_;   // 4M

// Scratch: exp(scores) and reciprocal batch-softmax denominators.
// __device__ globals are the sanctioned scratch mechanism (no allocs allowed).
__device__ float g_P[(size_t)B_ * N_ * N_];   // 268 MB
__device__ float g_rdenom[(size_t)N_ * N_];   // 16 MB

// -------------------------------------------------------------------------
// Kernel 1: for a (32q x 64k) tile, loop over all 16 batches:
//   S = (Q K^T) * 1/8 ;  P = exp(S) -> g_P ;  denom[q,k] += P (registers)
// Finally write rdenom = 1/denom. Each (q,k) is owned by exactly one thread.
// -------------------------------------------------------------------------
__global__ __launch_bounds__(128)
void k1_scores(const float* __restrict__ Q, const float* __restrict__ Km) {
    __shared__ float Qs[D_][36];   // [d][q]  (transposed; pad keeps 16B align)
    __shared__ float Ks[D_][68];   // [d][k]

    const int tid = threadIdx.x;
    const int q0 = blockIdx.y * 32;
    const int k0 = blockIdx.x * 64;
    const int ty = tid >> 4;   // 0..7  -> q micro row group (4 rows)
    const int tx = tid & 15;   // 0..15 -> k micro col group (4 cols)

    float denom[4][4];
#pragma unroll
    for (int i = 0; i < 4; i++)
#pragma unroll
        for (int j = 0; j < 4; j++) denom[i][j] = 0.0f;

    for (int b = 0; b < B_; b++) {
        // ---- stage Q tile (32 x 64), transposed into [d][q] ----
        const float* Qb = Q + ((size_t)b * N_ + q0) * D_;
#pragma unroll
        for (int it = 0; it < 4; it++) {
            int f = tid + it * 128;          // 0..511 float4s
            int q = f >> 4, d4 = f & 15;
            float4 v = *(const float4*)(Qb + q * D_ + d4 * 4);
            Qs[d4 * 4 + 0][q] = v.x;
            Qs[d4 * 4 + 1][q] = v.y;
            Qs[d4 * 4 + 2][q] = v.z;
            Qs[d4 * 4 + 3][q] = v.w;
        }
        // ---- stage K tile (64 x 64), transposed into [d][k] ----
        const float* Kb = Km + ((size_t)b * N_ + k0) * D_;
#pragma unroll
        for (int it = 0; it < 8; it++) {
            int f = tid + it * 128;          // 0..1023 float4s
            int k = f >> 4, d4 = f & 15;
            float4 v = *(const float4*)(Kb + k * D_ + d4 * 4);
            Ks[d4 * 4 + 0][k] = v.x;
            Ks[d4 * 4 + 1][k] = v.y;
            Ks[d4 * 4 + 2][k] = v.z;
            Ks[d4 * 4 + 3][k] = v.w;
        }
        __syncthreads();

        // ---- 32x64x64 fp32 tile GEMM, 4x4 per thread ----
        float acc[4][4];
#pragma unroll
        for (int i = 0; i < 4; i++)
#pragma unroll
            for (int j = 0; j < 4; j++) acc[i][j] = 0.0f;

#pragma unroll 16
        for (int d = 0; d < D_; d++) {
            float4 qv = *(const float4*)&Qs[d][ty * 4];
            float4 kv = *(const float4*)&Ks[d][tx * 4];
            float qa[4] = {qv.x, qv.y, qv.z, qv.w};
            float ka[4] = {kv.x, kv.y, kv.z, kv.w};
#pragma unroll
            for (int i = 0; i < 4; i++)
#pragma unroll
                for (int j = 0; j < 4; j++)
                    acc[i][j] += qa[i] * ka[j];
        }

        // ---- exp, accumulate denom, write P ----
        float* Pb = g_P + (size_t)b * N2;
#pragma unroll
        for (int i = 0; i < 4; i++) {
            float4 pv;
            pv.x = __expf(acc[i][0] * 0.125f);
            pv.y = __expf(acc[i][1] * 0.125f);
            pv.z = __expf(acc[i][2] * 0.125f);
            pv.w = __expf(acc[i][3] * 0.125f);
            denom[i][0] += pv.x;
            denom[i][1] += pv.y;
            denom[i][2] += pv.z;
            denom[i][3] += pv.w;
            *(float4*)(Pb + (size_t)(q0 + ty * 4 + i) * N_ + k0 + tx * 4) = pv;
        }
        __syncthreads();  // protect smem before next batch restage
    }

    // ---- write reciprocal denominators (exclusive ownership, no races) ----
#pragma unroll
    for (int i = 0; i < 4; i++) {
        float4 r;
        r.x = 1.0f / denom[i][0];
        r.y = 1.0f / denom[i][1];
        r.z = 1.0f / denom[i][2];
        r.w = 1.0f / denom[i][3];
        *(float4*)(g_rdenom + (size_t)(q0 + ty * 4 + i) * N_ + k0 + tx * 4) = r;
    }
}

// -------------------------------------------------------------------------
// Kernel 2: out[b] = (P[b] * rdenom) @ V[b]
// Block: 64q x 64d tile for one b; k in chunks of 64. Normalization folded
// into the P staging pass.
// -------------------------------------------------------------------------
__global__ __launch_bounds__(256)
void k2_out(const float* __restrict__ V, float* __restrict__ O) {
    __shared__ float As[64][68];   // [k][q]  attn tile (normalized)
    __shared__ float Vs[64][68];   // [k][d]

    const int tid = threadIdx.x;
    const int b = blockIdx.y;
    const int q0 = blockIdx.x * 64;
    const int ty = tid >> 4;   // 0..15 -> q group
    const int tx = tid & 15;   // 0..15 -> d group

    float acc[4][4];
#pragma unroll
    for (int i = 0; i < 4; i++)
#pragma unroll
        for (int j = 0; j < 4; j++) acc[i][j] = 0.0f;

    const float* Pb = g_P + (size_t)b * N2;
    const float* Vb = V + (size_t)b * N_ * D_;

    for (int kc = 0; kc < N_ / 64; kc++) {
        const int k0 = kc * 64;
        // ---- stage normalized attn tile (64q x 64k) transposed to [k][q] ----
#pragma unroll
        for (int it = 0; it < 4; it++) {
            int f = tid + it * 256;         // 0..1023 float4s
            int q = f >> 4, k4 = f & 15;
            size_t off = (size_t)(q0 + q) * N_ + k0 + k4 * 4;
            float4 p = *(const float4*)(Pb + off);
            float4 r = *(const float4*)(g_rdenom + off);
            As[k4 * 4 + 0][q] = p.x * r.x;
            As[k4 * 4 + 1][q] = p.y * r.y;
            As[k4 * 4 + 2][q] = p.z * r.z;
            As[k4 * 4 + 3][q] = p.w * r.w;
        }
        // ---- stage V tile (64k x 64d), natural orientation ----
#pragma unroll
        for (int it = 0; it < 4; it++) {
            int f = tid + it * 256;
            int k = f >> 4, d4 = f & 15;
            float4 v = *(const float4*)(Vb + (size_t)(k0 + k) * D_ + d4 * 4);
            *(float4*)&Vs[k][d4 * 4] = v;
        }
        __syncthreads();

#pragma unroll 16
        for (int k = 0; k < 64; k++) {
            float4 av = *(const float4*)&As[k][ty * 4];
            float4 vv = *(const float4*)&Vs[k][tx * 4];
            float aa[4] = {av.x, av.y, av.z, av.w};
            float va[4] = {vv.x, vv.y, vv.z, vv.w};
#pragma unroll
            for (int i = 0; i < 4; i++)
#pragma unroll
                for (int j = 0; j < 4; j++)
                    acc[i][j] += aa[i] * va[j];
        }
        __syncthreads();
    }

#pragma unroll
    for (int i = 0; i < 4; i++) {
        float4 o;
        o.x = acc[i][0];
        o.y = acc[i][1];
        o.z = acc[i][2];
        o.w = acc[i][3];
        *(float4*)(O + ((size_t)b * N_ + q0 + ty * 4 + i) * D_ + tx * 4) = o;
    }
}

// -------------------------------------------------------------------------
extern "C" void kernel_launch(void* const* d_in, const int* in_sizes, int n_in,
                              void* d_out, int out_size) {
    const float* Q = (const float*)d_in[0];
    const float* K = (const float*)d_in[1];
    const float* V = (const float*)d_in[2];
    float* O = (float*)d_out;

    dim3 g1(N_ / 64, N_ / 32);   // (k tiles, q tiles) = (32, 64)
    k1_scores<<<g1, 128>>>(Q, K);

    dim3 g2(N_ / 64, B_);        // (q tiles, batch) = (32, 16)
    k2_out<<<g2, 256>>>(V, O);
}

// round 2
// speedup vs baseline: 1.1100x; 1.1100x over previous
#include <cuda_runtime.h>
#include <cstddef>
#include <cstdint>

constexpr int B_ = 16;
constexpr int N_ = 2048;
constexpr int D_ = 64;
constexpr size_t N2 = (size_t)N_ * N_;

// Scratch (no allocations allowed -> __device__ globals)
__device__ float g_P[(size_t)B_ * N_ * N_];   // 268 MB: exp(scores)
__device__ float g_rdenom[(size_t)N_ * N_];   // 16 MB: 1/sum_b exp

// ---------------------------------------------------------------------------
// Kernel 1: tile = 64q x 128k, 128 threads, 8x8 micro-tile.
// Loop b: S = (Q*scale) K^T ; P = exp(S) -> g_P ; denom += P (registers).
// Swizzled smem, no padding: Qs[64d][64q], Ks[64d][128k].
// ---------------------------------------------------------------------------
__global__ __launch_bounds__(128, 3)
void k1_scores(const float* __restrict__ Q, const float* __restrict__ Km) {
    extern __shared__ float sm[];
    float* Qs = sm;            // 64*64
    float* Ks = sm + 64 * 64;  // 64*128

    const int tid = threadIdx.x;
    const int q0 = blockIdx.y * 64;
    const int k0 = blockIdx.x * 128;
    const int ty = tid >> 4;   // 0..7  : q group (8 rows)
    const int tx = tid & 15;   // 0..15 : k group (8 cols)

    float denom[8][8];
#pragma unroll
    for (int i = 0; i < 8; i++)
#pragma unroll
        for (int j = 0; j < 8; j++) denom[i][j] = 0.0f;

    for (int b = 0; b < B_; b++) {
        const float* Qb = Q + ((size_t)b * N_ + q0) * D_;
        const float* Kb = Km + ((size_t)b * N_ + k0) * D_;

        // ---- stage Q (64x64) -> Qs[d][q], scale folded, swizzled ----
#pragma unroll
        for (int it = 0; it < 8; it++) {
            int f = tid + it * 128;
            int q = f >> 4;        // 0..63
            int d4 = f & 15;       // 0..15 (d block)
            float4 v = *(const float4*)(Qb + q * D_ + d4 * 4);
            int qb = q >> 2, qi = q & 3;
            int pc = (((qb ^ d4) & 15) << 2) | qi;
            Qs[(d4 * 4 + 0) * 64 + pc] = v.x * 0.125f;
            Qs[(d4 * 4 + 1) * 64 + pc] = v.y * 0.125f;
            Qs[(d4 * 4 + 2) * 64 + pc] = v.z * 0.125f;
            Qs[(d4 * 4 + 3) * 64 + pc] = v.w * 0.125f;
        }
        // ---- stage K (128x64) -> Ks[d][k], swizzled ----
#pragma unroll
        for (int it = 0; it < 16; it++) {
            int f = tid + it * 128;
            int k = f >> 4;        // 0..127
            int d4 = f & 15;
            float4 v = *(const float4*)(Kb + k * D_ + d4 * 4);
            int kb = k >> 2, ki = k & 3;
            int pb = (kb & 16) | ((kb ^ d4) & 15);
            int pc = (pb << 2) | ki;
            Ks[(d4 * 4 + 0) * 128 + pc] = v.x;
            Ks[(d4 * 4 + 1) * 128 + pc] = v.y;
            Ks[(d4 * 4 + 2) * 128 + pc] = v.z;
            Ks[(d4 * 4 + 3) * 128 + pc] = v.w;
        }
        __syncthreads();

        float acc[8][8];
#pragma unroll
        for (int i = 0; i < 8; i++)
#pragma unroll
            for (int j = 0; j < 8; j++) acc[i][j] = 0.0f;

#pragma unroll 8
        for (int d = 0; d < D_; d++) {
            int d4 = d >> 2;
            int qb0 = ty * 2, qb1 = ty * 2 + 1;
            float4 qv0 = *(const float4*)&Qs[d * 64 + (((qb0 ^ d4) & 15) << 2)];
            float4 qv1 = *(const float4*)&Qs[d * 64 + (((qb1 ^ d4) & 15) << 2)];
            int kb0 = tx * 2, kb1 = tx * 2 + 1;
            float4 kv0 = *(const float4*)&Ks[d * 128 + ((((kb0 & 16) | ((kb0 ^ d4) & 15))) << 2)];
            float4 kv1 = *(const float4*)&Ks[d * 128 + ((((kb1 & 16) | ((kb1 ^ d4) & 15))) << 2)];
            float qa[8] = {qv0.x, qv0.y, qv0.z, qv0.w, qv1.x, qv1.y, qv1.z, qv1.w};
            float ka[8] = {kv0.x, kv0.y, kv0.z, kv0.w, kv1.x, kv1.y, kv1.z, kv1.w};
#pragma unroll
            for (int i = 0; i < 8; i++)
#pragma unroll
                for (int j = 0; j < 8; j++)
                    acc[i][j] += qa[i] * ka[j];
        }

        // ---- exp, accumulate denom, write P ----
        float* Pb = g_P + (size_t)b * N2;
#pragma unroll
        for (int i = 0; i < 8; i++) {
            float4 p0, p1;
            p0.x = __expf(acc[i][0]); p0.y = __expf(acc[i][1]);
            p0.z = __expf(acc[i][2]); p0.w = __expf(acc[i][3]);
            p1.x = __expf(acc[i][4]); p1.y = __expf(acc[i][5]);
            p1.z = __expf(acc[i][6]); p1.w = __expf(acc[i][7]);
            denom[i][0] += p0.x; denom[i][1] += p0.y;
            denom[i][2] += p0.z; denom[i][3] += p0.w;
            denom[i][4] += p1.x; denom[i][5] += p1.y;
            denom[i][6] += p1.z; denom[i][7] += p1.w;
            float* row = Pb + (size_t)(q0 + ty * 8 + i) * N_ + k0 + tx * 8;
            *(float4*)(row) = p0;
            *(float4*)(row + 4) = p1;
        }
        __syncthreads();
    }

    // ---- write reciprocal denominators (exclusive per-thread ownership) ----
#pragma unroll
    for (int i = 0; i < 8; i++) {
        float4 r0, r1;
        r0.x = 1.0f / denom[i][0]; r0.y = 1.0f / denom[i][1];
        r0.z = 1.0f / denom[i][2]; r0.w = 1.0f / denom[i][3];
        r1.x = 1.0f / denom[i][4]; r1.y = 1.0f / denom[i][5];
        r1.z = 1.0f / denom[i][6]; r1.w = 1.0f / denom[i][7];
        float* row = g_rdenom + (size_t)(q0 + ty * 8 + i) * N_ + k0 + tx * 8;
        *(float4*)(row) = r0;
        *(float4*)(row + 4) = r1;
    }
}

// ---------------------------------------------------------------------------
// Kernel 2: out[b] = (P[b] * rdenom) @ V[b]
// tile = 128q x 64d per (qtile, b) block, 128 threads, 8x8 micro-tile.
// k chunks of 64. As[64k][128q] swizzled; Vs[64k][68d] padded natural.
// ---------------------------------------------------------------------------
__global__ __launch_bounds__(128, 3)
void k2_out(const float* __restrict__ V, float* __restrict__ O) {
    extern __shared__ float sm[];
    float* As = sm;             // 64*128
    float* Vs = sm + 64 * 128;  // 64*68

    const int tid = threadIdx.x;
    const int b = blockIdx.y;
    const int q0 = blockIdx.x * 128;
    const int ty = tid >> 3;   // 0..15 : q group (8 rows)
    const int tx = tid & 7;    // 0..7  : d group (8 cols)

    float acc[8][8];
#pragma unroll
    for (int i = 0; i < 8; i++)
#pragma unroll
        for (int j = 0; j < 8; j++) acc[i][j] = 0.0f;

    const float* Pb = g_P + (size_t)b * N2;
    const float* Vb = V + (size_t)b * N_ * D_;

    for (int kc = 0; kc < N_ / 64; kc++) {
        const int k0 = kc * 64;

        // ---- stage normalized attn (128q x 64k) -> As[k][q], swizzled ----
#pragma unroll
        for (int it = 0; it < 16; it++) {
            int f = tid + it * 128;
            int q = f >> 4;        // 0..127
            int k4 = f & 15;       // k block
            size_t off = (size_t)(q0 + q) * N_ + k0 + k4 * 4;
            float4 p = *(const float4*)(Pb + off);
            float4 r = *(const float4*)(g_rdenom + off);
            int qb = q >> 2, qi = q & 3;
            int pb = (qb & 16) | ((qb ^ k4) & 15);
            int pc = (pb << 2) | qi;
            As[(k4 * 4 + 0) * 128 + pc] = p.x * r.x;
            As[(k4 * 4 + 1) * 128 + pc] = p.y * r.y;
            As[(k4 * 4 + 2) * 128 + pc] = p.z * r.z;
            As[(k4 * 4 + 3) * 128 + pc] = p.w * r.w;
        }
        // ---- stage V (64k x 64d) natural, padded rows ----
#pragma unroll
        for (int it = 0; it < 8; it++) {
            int f = tid + it * 128;
            int k = f >> 4;
            int d4 = f & 15;
            float4 v = *(const float4*)(Vb + (size_t)(k0 + k) * D_ + d4 * 4);
            *(float4*)&Vs[k * 68 + d4 * 4] = v;
        }
        __syncthreads();

#pragma unroll 8
        for (int k = 0; k < 64; k++) {
            int k4 = k >> 2;
            int qb0 = ty * 2, qb1 = ty * 2 + 1;
            float4 a0 = *(const float4*)&As[k * 128 + ((((qb0 & 16) | ((qb0 ^ k4) & 15))) << 2)];
            float4 a1 = *(const float4*)&As[k * 128 + ((((qb1 & 16) | ((qb1 ^ k4) & 15))) << 2)];
            float4 v0 = *(const float4*)&Vs[k * 68 + tx * 8];
            float4 v1 = *(const float4*)&Vs[k * 68 + tx * 8 + 4];
            float aa[8] = {a0.x, a0.y, a0.z, a0.w, a1.x, a1.y, a1.z, a1.w};
            float vv[8] = {v0.x, v0.y, v0.z, v0.w, v1.x, v1.y, v1.z, v1.w};
#pragma unroll
            for (int i = 0; i < 8; i++)
#pragma unroll
                for (int j = 0; j < 8; j++)
                    acc[i][j] += aa[i] * vv[j];
        }
        __syncthreads();
    }

#pragma unroll
    for (int i = 0; i < 8; i++) {
        float4 o0, o1;
        o0.x = acc[i][0]; o0.y = acc[i][1]; o0.z = acc[i][2]; o0.w = acc[i][3];
        o1.x = acc[i][4]; o1.y = acc[i][5]; o1.z = acc[i][6]; o1.w = acc[i][7];
        float* row = O + ((size_t)b * N_ + q0 + ty * 8 + i) * D_ + tx * 8;
        *(float4*)(row) = o0;
        *(float4*)(row + 4) = o1;
    }
}

// ---------------------------------------------------------------------------
extern "C" void kernel_launch(void* const* d_in, const int* in_sizes, int n_in,
                              void* d_out, int out_size) {
    const float* Q = (const float*)d_in[0];
    const float* K = (const float*)d_in[1];
    const float* V = (const float*)d_in[2];
    float* O = (float*)d_out;

    const int smem1 = (64 * 64 + 64 * 128) * 4;   // 49152
    const int smem2 = (64 * 128 + 64 * 68) * 4;   // 50176
    cudaFuncSetAttribute(k1_scores, cudaFuncAttributeMaxDynamicSharedMemorySize, smem1);
    cudaFuncSetAttribute(k2_out, cudaFuncAttributeMaxDynamicSharedMemorySize, smem2);

    dim3 g1(N_ / 128, N_ / 64);   // (16 k-tiles, 32 q-tiles)
    k1_scores<<<g1, 128, smem1>>>(Q, K);

    dim3 g2(N_ / 128, B_);        // (16 q-tiles, 16 batches)
    k2_out<<<g2, 128, smem2>>>(V, O);
}

// round 5
// speedup vs baseline: 2.1480x; 1.9352x over previous
#include <cuda_runtime.h>
#include <cuda_bf16.h>
#include <cstdint>
#include <cstddef>

constexpr int B_ = 16, N_ = 2048, D_ = 64;
constexpr size_t ND = (size_t)N_ * D_;
constexpr size_t N2 = (size_t)N_ * N_;

// ---- scratch (__device__ globals; no allocations allowed) ----
__device__ float g_P[(size_t)B_ * N2];        // 268MB exp(scores)
__device__ float g_rdenom[N2];                // 16MB
__device__ __nv_bfloat16 g_Qh[(size_t)B_ * ND];
__device__ __nv_bfloat16 g_Ql[(size_t)B_ * ND];
__device__ __nv_bfloat16 g_Kh[(size_t)B_ * ND];
__device__ __nv_bfloat16 g_Kl[(size_t)B_ * ND];
__device__ __nv_bfloat16 g_Vth[(size_t)B_ * ND];  // [b][d][k]
__device__ __nv_bfloat16 g_Vtl[(size_t)B_ * ND];

#define SW128(o) ((o) ^ (((o) >> 3) & 0x70))

__device__ __forceinline__ uint32_t smem_u32(const void* p) {
    uint32_t a;
    asm("{ .reg .u64 t; cvta.to.shared.u64 t, %1; cvt.u32.u64 %0, t; }" : "=r"(a) : "l"(p));
    return a;
}
__device__ __forceinline__ void ldmx4(uint32_t* r, uint32_t addr) {
    asm volatile("ldmatrix.sync.aligned.m8n8.x4.shared.b16 {%0,%1,%2,%3}, [%4];"
                 : "=r"(r[0]), "=r"(r[1]), "=r"(r[2]), "=r"(r[3]) : "r"(addr));
}
__device__ __forceinline__ void mma16816(float* d, const uint32_t* a, uint32_t b0, uint32_t b1) {
    asm volatile(
        "mma.sync.aligned.m16n8k16.row.col.f32.bf16.bf16.f32 "
        "{%0,%1,%2,%3}, {%4,%5,%6,%7}, {%8,%9}, {%0,%1,%2,%3};"
        : "+f"(d[0]), "+f"(d[1]), "+f"(d[2]), "+f"(d[3])
        : "r"(a[0]), "r"(a[1]), "r"(a[2]), "r"(a[3]), "r"(b0), "r"(b1));
}
__device__ __forceinline__ void split2(float a, float b, uint32_t& h, uint32_t& l) {
    __nv_bfloat16 ha = __float2bfloat16(a), hb = __float2bfloat16(b);
    float la = a - __bfloat162float(ha), lb = b - __bfloat162float(hb);
    __nv_bfloat16 lae = __float2bfloat16(la), lbe = __float2bfloat16(lb);
    h = (uint32_t)__bfloat16_as_ushort(ha) | ((uint32_t)__bfloat16_as_ushort(hb) << 16);
    l = (uint32_t)__bfloat16_as_ushort(lae) | ((uint32_t)__bfloat16_as_ushort(lbe) << 16);
}

// ===========================================================================
// k0a: split Q/K (fp32 -> bf16 hi/lo); scale folded into Q
// ===========================================================================
__global__ __launch_bounds__(256) void k0_split(const float* __restrict__ in, int sel, float scale) {
    __nv_bfloat16* hi = sel ? g_Kh : g_Qh;
    __nv_bfloat16* lo = sel ? g_Kl : g_Ql;
    size_t i = (size_t)blockIdx.x * blockDim.x + threadIdx.x;   // unit of 8 floats
    if (i >= (size_t)B_ * ND / 8) return;
    float4 a = ((const float4*)in)[i * 2];
    float4 b = ((const float4*)in)[i * 2 + 1];
    uint32_t h[4], l[4];
    split2(a.x * scale, a.y * scale, h[0], l[0]);
    split2(a.z * scale, a.w * scale, h[1], l[1]);
    split2(b.x * scale, b.y * scale, h[2], l[2]);
    split2(b.z * scale, b.w * scale, h[3], l[3]);
    ((uint4*)hi)[i] = make_uint4(h[0], h[1], h[2], h[3]);
    ((uint4*)lo)[i] = make_uint4(l[0], l[1], l[2], l[3]);
}

// ===========================================================================
// k0b: transpose V [b][k][d] -> Vt [b][d][k], bf16 hi/lo split
// ===========================================================================
__global__ __launch_bounds__(256) void k0_vt(const float* __restrict__ V) {
    __shared__ float smv[64][65];
    const int b = blockIdx.y, k0 = blockIdx.x * 64;
    const int t = threadIdx.x;
    const float* Vb = V + ((size_t)b * N_ + k0) * D_;
#pragma unroll
    for (int it = 0; it < 4; it++) {
        int f = t + it * 256;
        int k = f >> 4, d4 = f & 15;
        float4 v = *(const float4*)(Vb + k * D_ + d4 * 4);
        smv[k][d4 * 4 + 0] = v.x;
        smv[k][d4 * 4 + 1] = v.y;
        smv[k][d4 * 4 + 2] = v.z;
        smv[k][d4 * 4 + 3] = v.w;
    }
    __syncthreads();
    const int d = t >> 2, kg = t & 3;
    uint32_t h[8], l[8];
#pragma unroll
    for (int j = 0; j < 8; j++)
        split2(smv[kg * 16 + j * 2][d], smv[kg * 16 + j * 2 + 1][d], h[j], l[j]);
    size_t off = ((size_t)b * D_ + d) * N_ + k0 + kg * 16;
    *(uint4*)(g_Vth + off)     = make_uint4(h[0], h[1], h[2], h[3]);
    *(uint4*)(g_Vth + off + 8) = make_uint4(h[4], h[5], h[6], h[7]);
    *(uint4*)(g_Vtl + off)     = make_uint4(l[0], l[1], l[2], l[3]);
    *(uint4*)(g_Vtl + off + 8) = make_uint4(l[4], l[5], l[6], l[7]);
}

// ===========================================================================
// k1: scores. Block 256thr = 8 warps, tile 128q x 64k, warp = 32q x 32k.
// Loop b: stage Q/K hi-lo into SW128 smem, 3-split HMMA, exp in fragments,
// per-thread denom accumulation; write P; epilogue writes rdenom.
// smem map: Qh@0 (16K), Ql@16384, Kh@32768 (8K), Kl@40960 => 48KB
// ===========================================================================
__global__ __launch_bounds__(256, 2) void k1_scores() {
    __shared__ __align__(128) uint8_t smem[49152];
    const uint32_t sb = smem_u32(smem);
    const int tid = threadIdx.x;
    const int lane = tid & 31, w = tid >> 5;
    const int q0 = blockIdx.y * 128, k0 = blockIdx.x * 64;
    const int wq = w >> 1, wk = w & 1;           // warp grid 4x2
    const int arow = wq * 32 + (lane & 15);      // ldmatrix A row
    const int brow = wk * 32 + (lane & 15);      // ldmatrix B row base
    const int acol = (lane >> 4) * 16;           // byte col within k-step

    float denom[2][4][4];
#pragma unroll
    for (int mt = 0; mt < 2; mt++)
#pragma unroll
        for (int nt = 0; nt < 4; nt++)
#pragma unroll
            for (int r = 0; r < 4; r++) denom[mt][nt][r] = 0.0f;

    for (int b = 0; b < B_; b++) {
        // ---- stage tiles ----
        const size_t qbase = (size_t)b * ND + (size_t)(q0) * D_;
        const size_t kbase = (size_t)b * ND + (size_t)(k0) * D_;
#pragma unroll
        for (int it = 0; it < 4; it++) {
            int u = tid + it * 256;
            int q = u >> 3, g = u & 7;
            uint32_t dst = SW128((uint32_t)(q * 128 + g * 16));
            *(uint4*)(smem + dst)         = *(const uint4*)(g_Qh + qbase + q * D_ + g * 8);
            *(uint4*)(smem + 16384 + dst) = *(const uint4*)(g_Ql + qbase + q * D_ + g * 8);
        }
#pragma unroll
        for (int it = 0; it < 2; it++) {
            int u = tid + it * 256;
            int k = u >> 3, g = u & 7;
            uint32_t dst = SW128((uint32_t)(k * 128 + g * 16));
            *(uint4*)(smem + 32768 + dst) = *(const uint4*)(g_Kh + kbase + k * D_ + g * 8);
            *(uint4*)(smem + 40960 + dst) = *(const uint4*)(g_Kl + kbase + k * D_ + g * 8);
        }
        __syncthreads();

        // ---- 3-split HMMA: D = Qh*Kh + Qh*Kl + Ql*Kh ----
        float Dc[2][4][4];
#pragma unroll
        for (int mt = 0; mt < 2; mt++)
#pragma unroll
            for (int nt = 0; nt < 4; nt++)
#pragma unroll
                for (int r = 0; r < 4; r++) Dc[mt][nt][r] = 0.0f;

#pragma unroll
        for (int sp = 0; sp < 3; sp++) {
            const uint32_t abase = sb + (sp == 2 ? 16384u : 0u);
            const uint32_t bbase = sb + (sp == 1 ? 40960u : 32768u);
#pragma unroll
            for (int ks = 0; ks < 4; ks++) {
                uint32_t a[2][4], bm[2][4];
#pragma unroll
                for (int mt = 0; mt < 2; mt++)
                    ldmx4(a[mt], abase + SW128((uint32_t)((arow + mt * 16) * 128 + ks * 32 + acol)));
#pragma unroll
                for (int np = 0; np < 2; np++)
                    ldmx4(bm[np], bbase + SW128((uint32_t)((brow + np * 16) * 128 + ks * 32 + acol)));
#pragma unroll
                for (int mt = 0; mt < 2; mt++)
#pragma unroll
                    for (int np = 0; np < 2; np++) {
                        mma16816(Dc[mt][np * 2],     a[mt], bm[np][0], bm[np][2]);
                        mma16816(Dc[mt][np * 2 + 1], a[mt], bm[np][1], bm[np][3]);
                    }
            }
        }
        __syncthreads();   // ldmatrix done before next b restage

        // ---- exp + denom + P store (fragment-exclusive ownership) ----
        float* Pb = g_P + (size_t)b * N2;
#pragma unroll
        for (int mt = 0; mt < 2; mt++) {
            int r0 = q0 + wq * 32 + mt * 16 + (lane >> 2);
#pragma unroll
            for (int nt = 0; nt < 4; nt++) {
                int cc = k0 + wk * 32 + nt * 8 + 2 * (lane & 3);
                float e0 = __expf(Dc[mt][nt][0]);
                float e1 = __expf(Dc[mt][nt][1]);
                float e2 = __expf(Dc[mt][nt][2]);
                float e3 = __expf(Dc[mt][nt][3]);
                denom[mt][nt][0] += e0; denom[mt][nt][1] += e1;
                denom[mt][nt][2] += e2; denom[mt][nt][3] += e3;
                *(float2*)(Pb + (size_t)r0 * N_ + cc)       = make_float2(e0, e1);
                *(float2*)(Pb + (size_t)(r0 + 8) * N_ + cc) = make_float2(e2, e3);
            }
        }
    }

    // ---- rdenom ----
#pragma unroll
    for (int mt = 0; mt < 2; mt++) {
        int r0 = q0 + wq * 32 + mt * 16 + (lane >> 2);
#pragma unroll
        for (int nt = 0; nt < 4; nt++) {
            int cc = k0 + wk * 32 + nt * 8 + 2 * (lane & 3);
            *(float2*)(g_rdenom + (size_t)r0 * N_ + cc) =
                make_float2(1.0f / denom[mt][nt][0], 1.0f / denom[mt][nt][1]);
            *(float2*)(g_rdenom + (size_t)(r0 + 8) * N_ + cc) =
                make_float2(1.0f / denom[mt][nt][2], 1.0f / denom[mt][nt][3]);
        }
    }
}

// ===========================================================================
// k2: out[b] = (P[b]*rdenom) @ V[b]. Block 256thr, tile 128q x 64d,
// warp = 32q x 32d, k-chunks of 64, persistent fp32 fragments.
// smem map: Ah@0 (16K), Al@16384, Bh@32768 (8K), Bl@40960 => 48KB
// ===========================================================================
__global__ __launch_bounds__(256, 2) void k2_out(float* __restrict__ O) {
    __shared__ __align__(128) uint8_t smem[49152];
    const uint32_t sb = smem_u32(smem);
    const int tid = threadIdx.x;
    const int lane = tid & 31, w = tid >> 5;
    const int b = blockIdx.x;                   // b fastest => rdenom L2 reuse
    const int q0 = blockIdx.y * 128;
    const int wq = w >> 1, wd = w & 1;
    const int arow = wq * 32 + (lane & 15);
    const int brow = wd * 32 + (lane & 15);
    const int acol = (lane >> 4) * 16;

    const float* Pb = g_P + (size_t)b * N2;

    float Dc[2][4][4];
#pragma unroll
    for (int mt = 0; mt < 2; mt++)
#pragma unroll
        for (int nt = 0; nt < 4; nt++)
#pragma unroll
            for (int r = 0; r < 4; r++) Dc[mt][nt][r] = 0.0f;

    for (int c = 0; c < 32; c++) {
        const int kc = c * 64;
        // ---- stage A = normalize(P)*split, B = Vt hi/lo ----
#pragma unroll
        for (int it = 0; it < 4; it++) {
            int u = tid + it * 256;
            int q = u >> 3, g = u & 7;
            size_t off = (size_t)(q0 + q) * N_ + kc + g * 8;
            float4 p0 = *(const float4*)(Pb + off);
            float4 p1 = *(const float4*)(Pb + off + 4);
            float4 r0 = *(const float4*)(g_rdenom + off);
            float4 r1 = *(const float4*)(g_rdenom + off + 4);
            uint32_t h[4], l[4];
            split2(p0.x * r0.x, p0.y * r0.y, h[0], l[0]);
            split2(p0.z * r0.z, p0.w * r0.w, h[1], l[1]);
            split2(p1.x * r1.x, p1.y * r1.y, h[2], l[2]);
            split2(p1.z * r1.z, p1.w * r1.w, h[3], l[3]);
            uint32_t dst = SW128((uint32_t)(q * 128 + g * 16));
            *(uint4*)(smem + dst)         = make_uint4(h[0], h[1], h[2], h[3]);
            *(uint4*)(smem + 16384 + dst) = make_uint4(l[0], l[1], l[2], l[3]);
        }
#pragma unroll
        for (int it = 0; it < 2; it++) {
            int u = tid + it * 256;
            int d = u >> 3, g = u & 7;
            size_t off = ((size_t)b * D_ + d) * N_ + kc + g * 8;
            uint32_t dst = SW128((uint32_t)(d * 128 + g * 16));
            *(uint4*)(smem + 32768 + dst) = *(const uint4*)(g_Vth + off);
            *(uint4*)(smem + 40960 + dst) = *(const uint4*)(g_Vtl + off);
        }
        __syncthreads();

#pragma unroll
        for (int sp = 0; sp < 3; sp++) {
            const uint32_t abase = sb + (sp == 2 ? 16384u : 0u);
            const uint32_t bbase = sb + (sp == 1 ? 40960u : 32768u);
#pragma unroll
            for (int ks = 0; ks < 4; ks++) {
                uint32_t a[2][4], bm[2][4];
#pragma unroll
                for (int mt = 0; mt < 2; mt++)
                    ldmx4(a[mt], abase + SW128((uint32_t)((arow + mt * 16) * 128 + ks * 32 + acol)));
#pragma unroll
                for (int np = 0; np < 2; np++)
                    ldmx4(bm[np], bbase + SW128((uint32_t)((brow + np * 16) * 128 + ks * 32 + acol)));
#pragma unroll
                for (int mt = 0; mt < 2; mt++)
#pragma unroll
                    for (int np = 0; np < 2; np++) {
                        mma16816(Dc[mt][np * 2],     a[mt], bm[np][0], bm[np][2]);
                        mma16816(Dc[mt][np * 2 + 1], a[mt], bm[np][1], bm[np][3]);
                    }
            }
        }
        __syncthreads();
    }

    // ---- epilogue: write O ----
#pragma unroll
    for (int mt = 0; mt < 2; mt++) {
        int r0 = q0 + wq * 32 + mt * 16 + (lane >> 2);
#pragma unroll
        for (int nt = 0; nt < 4; nt++) {
            int cc = wd * 32 + nt * 8 + 2 * (lane & 3);
            *(float2*)(O + ((size_t)b * N_ + r0) * D_ + cc) =
                make_float2(Dc[mt][nt][0], Dc[mt][nt][1]);
            *(float2*)(O + ((size_t)b * N_ + r0 + 8) * D_ + cc) =
                make_float2(Dc[mt][nt][2], Dc[mt][nt][3]);
        }
    }
}

// ===========================================================================
extern "C" void kernel_launch(void* const* d_in, const int* in_sizes, int n_in,
                              void* d_out, int out_size) {
    const float* Q = (const float*)d_in[0];
    const float* K = (const float*)d_in[1];
    const float* V = (const float*)d_in[2];
    float* O = (float*)d_out;

    const int n8 = (int)((size_t)B_ * ND / 8);          // 262144
    k0_split<<<n8 / 256, 256>>>(Q, 0, 0.125f);
    k0_split<<<n8 / 256, 256>>>(K, 1, 1.0f);
    k0_vt<<<dim3(N_ / 64, B_), 256>>>(V);

    k1_scores<<<dim3(N_ / 64, N_ / 128), 256>>>();      // 32 k-tiles x 16 q-tiles
    k2_out<<<dim3(B_, N_ / 128), 256>>>(O);             // 16 b x 16 q-tiles
}

// round 7
// speedup vs baseline: 2.8865x; 1.3438x over previous
#include <cuda_runtime.h>
#include <cuda_bf16.h>
#include <cstdint>
#include <cstddef>

constexpr int B_ = 16, N_ = 2048, D_ = 64;
constexpr size_t ND = (size_t)N_ * D_;
constexpr size_t N2 = (size_t)N_ * N_;

// ---- scratch (__device__ globals; no allocations allowed) ----
__device__ float g_P[(size_t)B_ * N2];        // 268MB exp(scores)
__device__ float g_rdenom[N2];                // 16MB
__device__ __nv_bfloat16 g_Qh[(size_t)B_ * ND];
__device__ __nv_bfloat16 g_Ql[(size_t)B_ * ND];
__device__ __nv_bfloat16 g_Kh[(size_t)B_ * ND];
__device__ __nv_bfloat16 g_Kl[(size_t)B_ * ND];
__device__ __nv_bfloat16 g_Vth[(size_t)B_ * ND];  // [b][d][k]
__device__ __nv_bfloat16 g_Vtl[(size_t)B_ * ND];

#define SW128(o) ((o) ^ (((o) >> 3) & 0x70))

__device__ __forceinline__ uint32_t smem_u32(const void* p) {
    uint32_t a;
    asm("{ .reg .u64 t; cvta.to.shared.u64 t, %1; cvt.u32.u64 %0, t; }" : "=r"(a) : "l"(p));
    return a;
}
__device__ __forceinline__ void ldmx4(uint32_t* r, uint32_t addr) {
    asm volatile("ldmatrix.sync.aligned.m8n8.x4.shared.b16 {%0,%1,%2,%3}, [%4];"
                 : "=r"(r[0]), "=r"(r[1]), "=r"(r[2]), "=r"(r[3]) : "r"(addr));
}
__device__ __forceinline__ void mma16816(float* d, const uint32_t* a, uint32_t b0, uint32_t b1) {
    asm volatile(
        "mma.sync.aligned.m16n8k16.row.col.f32.bf16.bf16.f32 "
        "{%0,%1,%2,%3}, {%4,%5,%6,%7}, {%8,%9}, {%0,%1,%2,%3};"
        : "+f"(d[0]), "+f"(d[1]), "+f"(d[2]), "+f"(d[3])
        : "r"(a[0]), "r"(a[1]), "r"(a[2]), "r"(a[3]), "r"(b0), "r"(b1));
}
__device__ __forceinline__ void split2(float a, float b, uint32_t& h, uint32_t& l) {
    __nv_bfloat16 ha = __float2bfloat16(a), hb = __float2bfloat16(b);
    float la = a - __bfloat162float(ha), lb = b - __bfloat162float(hb);
    __nv_bfloat16 lae = __float2bfloat16(la), lbe = __float2bfloat16(lb);
    h = (uint32_t)__bfloat16_as_ushort(ha) | ((uint32_t)__bfloat16_as_ushort(hb) << 16);
    l = (uint32_t)__bfloat16_as_ushort(lae) | ((uint32_t)__bfloat16_as_ushort(lbe) << 16);
}
__device__ __forceinline__ void cp16(uint32_t dst, const void* src) {
    asm volatile("cp.async.cg.shared.global [%0], [%1], 16;" :: "r"(dst), "l"(src));
}
__device__ __forceinline__ void cp_commit() {
    asm volatile("cp.async.commit_group;" ::: "memory");
}

// ===========================================================================
// k0a: split Q/K (fp32 -> bf16 hi/lo); scale folded into Q
// ===========================================================================
__global__ __launch_bounds__(256) void k0_split(const float* __restrict__ in, int sel, float scale) {
    __nv_bfloat16* hi = sel ? g_Kh : g_Qh;
    __nv_bfloat16* lo = sel ? g_Kl : g_Ql;
    size_t i = (size_t)blockIdx.x * blockDim.x + threadIdx.x;   // unit of 8 floats
    if (i >= (size_t)B_ * ND / 8) return;
    float4 a = ((const float4*)in)[i * 2];
    float4 b = ((const float4*)in)[i * 2 + 1];
    uint32_t h[4], l[4];
    split2(a.x * scale, a.y * scale, h[0], l[0]);
    split2(a.z * scale, a.w * scale, h[1], l[1]);
    split2(b.x * scale, b.y * scale, h[2], l[2]);
    split2(b.z * scale, b.w * scale, h[3], l[3]);
    ((uint4*)hi)[i] = make_uint4(h[0], h[1], h[2], h[3]);
    ((uint4*)lo)[i] = make_uint4(l[0], l[1], l[2], l[3]);
}

// ===========================================================================
// k0b: transpose V [b][k][d] -> Vt [b][d][k], bf16 hi/lo split
// ===========================================================================
__global__ __launch_bounds__(256) void k0_vt(const float* __restrict__ V) {
    __shared__ float smv[64][65];
    const int b = blockIdx.y, k0 = blockIdx.x * 64;
    const int t = threadIdx.x;
    const float* Vb = V + ((size_t)b * N_ + k0) * D_;
#pragma unroll
    for (int it = 0; it < 4; it++) {
        int f = t + it * 256;
        int k = f >> 4, d4 = f & 15;
        float4 v = *(const float4*)(Vb + k * D_ + d4 * 4);
        smv[k][d4 * 4 + 0] = v.x;
        smv[k][d4 * 4 + 1] = v.y;
        smv[k][d4 * 4 + 2] = v.z;
        smv[k][d4 * 4 + 3] = v.w;
    }
    __syncthreads();
    const int d = t >> 2, kg = t & 3;
    uint32_t h[8], l[8];
#pragma unroll
    for (int j = 0; j < 8; j++)
        split2(smv[kg * 16 + j * 2][d], smv[kg * 16 + j * 2 + 1][d], h[j], l[j]);
    size_t off = ((size_t)b * D_ + d) * N_ + k0 + kg * 16;
    *(uint4*)(g_Vth + off)     = make_uint4(h[0], h[1], h[2], h[3]);
    *(uint4*)(g_Vth + off + 8) = make_uint4(h[4], h[5], h[6], h[7]);
    *(uint4*)(g_Vtl + off)     = make_uint4(l[0], l[1], l[2], l[3]);
    *(uint4*)(g_Vtl + off + 8) = make_uint4(l[4], l[5], l[6], l[7]);
}

// ---------------------------------------------------------------------------
// Shared-fragment 3-split MMA phase. Buffer layout (within one 48KB buffer):
//   Ah@+0 (16K), Al@+16384, Bh@+32768 (8K), Bl@+40960
// Products: Ah*Bh, Al*Bh, Ah*Bl -> 8 ldmx4 per ks instead of 12.
// ---------------------------------------------------------------------------
__device__ __forceinline__ void mma_phase(uint32_t buf, float Dc[2][4][4],
                                          int arow, int brow, int acol) {
#pragma unroll
    for (int ks = 0; ks < 4; ks++) {
        uint32_t aH[2][4], bH[2][4];
#pragma unroll
        for (int mt = 0; mt < 2; mt++)
            ldmx4(aH[mt], buf + SW128((uint32_t)((arow + mt * 16) * 128 + ks * 32 + acol)));
#pragma unroll
        for (int np = 0; np < 2; np++)
            ldmx4(bH[np], buf + 32768 + SW128((uint32_t)((brow + np * 16) * 128 + ks * 32 + acol)));
#pragma unroll
        for (int mt = 0; mt < 2; mt++)
#pragma unroll
            for (int np = 0; np < 2; np++) {
                mma16816(Dc[mt][np * 2],     aH[mt], bH[np][0], bH[np][2]);
                mma16816(Dc[mt][np * 2 + 1], aH[mt], bH[np][1], bH[np][3]);
            }
        {   // Al * Bh (reuse bH)
            uint32_t aL[2][4];
#pragma unroll
            for (int mt = 0; mt < 2; mt++)
                ldmx4(aL[mt], buf + 16384 + SW128((uint32_t)((arow + mt * 16) * 128 + ks * 32 + acol)));
#pragma unroll
            for (int mt = 0; mt < 2; mt++)
#pragma unroll
                for (int np = 0; np < 2; np++) {
                    mma16816(Dc[mt][np * 2],     aL[mt], bH[np][0], bH[np][2]);
                    mma16816(Dc[mt][np * 2 + 1], aL[mt], bH[np][1], bH[np][3]);
                }
        }
        {   // Ah * Bl (reuse aH)
            uint32_t bL[2][4];
#pragma unroll
            for (int np = 0; np < 2; np++)
                ldmx4(bL[np], buf + 40960 + SW128((uint32_t)((brow + np * 16) * 128 + ks * 32 + acol)));
#pragma unroll
            for (int mt = 0; mt < 2; mt++)
#pragma unroll
                for (int np = 0; np < 2; np++) {
                    mma16816(Dc[mt][np * 2],     aH[mt], bL[np][0], bL[np][2]);
                    mma16816(Dc[mt][np * 2 + 1], aH[mt], bL[np][1], bL[np][3]);
                }
        }
    }
}

// ===========================================================================
// k1: scores. 256 thr, tile 128q x 64k, warp 32q x 32k. Double-buffered
// cp.async staging: batch b+1 in flight during batch b's MMA+exp phase.
// smem: two 48KB buffers (Qh/Ql/Kh/Kl).
// ===========================================================================
__device__ __forceinline__ void k1_stage(uint32_t buf, int tid, size_t qbase, size_t kbase) {
#pragma unroll
    for (int it = 0; it < 4; it++) {
        int u = tid + it * 256;
        int q = u >> 3, g = u & 7;
        uint32_t dst = buf + SW128((uint32_t)(q * 128 + g * 16));
        cp16(dst,         g_Qh + qbase + q * D_ + g * 8);
        cp16(dst + 16384, g_Ql + qbase + q * D_ + g * 8);
    }
#pragma unroll
    for (int it = 0; it < 2; it++) {
        int u = tid + it * 256;
        int k = u >> 3, g = u & 7;
        uint32_t dst = buf + 32768 + SW128((uint32_t)(k * 128 + g * 16));
        cp16(dst,        g_Kh + kbase + k * D_ + g * 8);
        cp16(dst + 8192, g_Kl + kbase + k * D_ + g * 8);
    }
    cp_commit();
}

__global__ __launch_bounds__(256, 2) void k1_scores() {
    extern __shared__ __align__(128) uint8_t smem[];   // 98304
    const uint32_t sb = smem_u32(smem);
    const int tid = threadIdx.x;
    const int lane = tid & 31, w = tid >> 5;
    const int q0 = blockIdx.y * 128, k0 = blockIdx.x * 64;
    const int wq = w >> 1, wk = w & 1;
    const int arow = wq * 32 + (lane & 15);
    const int brow = wk * 32 + (lane & 15);
    const int acol = (lane >> 4) * 16;

    float denom[2][4][4];
#pragma unroll
    for (int mt = 0; mt < 2; mt++)
#pragma unroll
        for (int nt = 0; nt < 4; nt++)
#pragma unroll
            for (int r = 0; r < 4; r++) denom[mt][nt][r] = 0.0f;

    k1_stage(sb,         tid, (size_t)0 * ND + (size_t)q0 * D_, (size_t)0 * ND + (size_t)k0 * D_);
    k1_stage(sb + 49152, tid, (size_t)1 * ND + (size_t)q0 * D_, (size_t)1 * ND + (size_t)k0 * D_);

    for (int b = 0; b < B_; b++) {
        const uint32_t buf = sb + (b & 1) * 49152;
        if (b < B_ - 1) asm volatile("cp.async.wait_group 1;" ::: "memory");
        else            asm volatile("cp.async.wait_group 0;" ::: "memory");
        __syncthreads();

        float Dc[2][4][4];
#pragma unroll
        for (int mt = 0; mt < 2; mt++)
#pragma unroll
            for (int nt = 0; nt < 4; nt++)
#pragma unroll
                for (int r = 0; r < 4; r++) Dc[mt][nt][r] = 0.0f;

        mma_phase(buf, Dc, arow, brow, acol);

        // ---- exp + denom + P store (fragment-exclusive ownership) ----
        float* Pb = g_P + (size_t)b * N2;
#pragma unroll
        for (int mt = 0; mt < 2; mt++) {
            int r0 = q0 + wq * 32 + mt * 16 + (lane >> 2);
#pragma unroll
            for (int nt = 0; nt < 4; nt++) {
                int cc = k0 + wk * 32 + nt * 8 + 2 * (lane & 3);
                float e0 = __expf(Dc[mt][nt][0]);
                float e1 = __expf(Dc[mt][nt][1]);
                float e2 = __expf(Dc[mt][nt][2]);
                float e3 = __expf(Dc[mt][nt][3]);
                denom[mt][nt][0] += e0; denom[mt][nt][1] += e1;
                denom[mt][nt][2] += e2; denom[mt][nt][3] += e3;
                *(float2*)(Pb + (size_t)r0 * N_ + cc)       = make_float2(e0, e1);
                *(float2*)(Pb + (size_t)(r0 + 8) * N_ + cc) = make_float2(e2, e3);
            }
        }
        __syncthreads();
        if (b + 2 < B_)
            k1_stage(buf, tid, (size_t)(b + 2) * ND + (size_t)q0 * D_,
                               (size_t)(b + 2) * ND + (size_t)k0 * D_);
    }

    // ---- rdenom ----
#pragma unroll
    for (int mt = 0; mt < 2; mt++) {
        int r0 = q0 + wq * 32 + mt * 16 + (lane >> 2);
#pragma unroll
        for (int nt = 0; nt < 4; nt++) {
            int cc = k0 + wk * 32 + nt * 8 + 2 * (lane & 3);
            *(float2*)(g_rdenom + (size_t)r0 * N_ + cc) =
                make_float2(1.0f / denom[mt][nt][0], 1.0f / denom[mt][nt][1]);
            *(float2*)(g_rdenom + (size_t)(r0 + 8) * N_ + cc) =
                make_float2(1.0f / denom[mt][nt][2], 1.0f / denom[mt][nt][3]);
        }
    }
}

// ===========================================================================
// k2: out[b] = (P[b]*rdenom) @ V[b]. 256 thr, tile 128q x 64d, warp 32q x 32d.
// Double-buffered: V via cp.async, P via register-prefetch + split2 staging,
// both overlapping the MMA phase.
// ===========================================================================
__device__ __forceinline__ void k2_stageB(uint32_t buf, int tid, size_t vbase) {
#pragma unroll
    for (int it = 0; it < 2; it++) {
        int u = tid + it * 256;
        int d = u >> 3, g = u & 7;
        uint32_t dst = buf + 32768 + SW128((uint32_t)(d * 128 + g * 16));
        cp16(dst,        g_Vth + vbase + (size_t)d * N_ + g * 8);
        cp16(dst + 8192, g_Vtl + vbase + (size_t)d * N_ + g * 8);
    }
    cp_commit();
}

__global__ __launch_bounds__(256, 2) void k2_out(float* __restrict__ O) {
    extern __shared__ __align__(128) uint8_t smem[];   // 98304
    const uint32_t sb = smem_u32(smem);
    const int tid = threadIdx.x;
    const int lane = tid & 31, w = tid >> 5;
    const int b = blockIdx.x;                   // b fastest => rdenom L2 reuse
    const int q0 = blockIdx.y * 128;
    const int wq = w >> 1, wd = w & 1;
    const int arow = wq * 32 + (lane & 15);
    const int brow = wd * 32 + (lane & 15);
    const int acol = (lane >> 4) * 16;

    const float* Pb = g_P + (size_t)b * N2;
    const size_t vb0 = (size_t)b * ND;

    // per-thread staging coordinates (it = 0..3)
    int sq[4], sg[4];
#pragma unroll
    for (int it = 0; it < 4; it++) {
        int u = tid + it * 256;
        sq[it] = u >> 3;
        sg[it] = u & 7;
    }

    // ---- prologue: stage chunk 0 into buffer 0 ----
#pragma unroll
    for (int it = 0; it < 4; it++) {
        size_t off = (size_t)(q0 + sq[it]) * N_ + sg[it] * 8;
        float4 p0 = *(const float4*)(Pb + off);
        float4 p1 = *(const float4*)(Pb + off + 4);
        float4 r0 = *(const float4*)(g_rdenom + off);
        float4 r1 = *(const float4*)(g_rdenom + off + 4);
        uint32_t h[4], l[4];
        split2(p0.x * r0.x, p0.y * r0.y, h[0], l[0]);
        split2(p0.z * r0.z, p0.w * r0.w, h[1], l[1]);
        split2(p1.x * r1.x, p1.y * r1.y, h[2], l[2]);
        split2(p1.z * r1.z, p1.w * r1.w, h[3], l[3]);
        uint32_t dsw = SW128((uint32_t)(sq[it] * 128 + sg[it] * 16));
        *(uint4*)(smem + dsw)         = make_uint4(h[0], h[1], h[2], h[3]);
        *(uint4*)(smem + dsw + 16384) = make_uint4(l[0], l[1], l[2], l[3]);
    }
    k2_stageB(sb, tid, vb0);
    asm volatile("cp.async.wait_group 0;" ::: "memory");
    __syncthreads();

    float Dc[2][4][4];
#pragma unroll
    for (int mt = 0; mt < 2; mt++)
#pragma unroll
        for (int nt = 0; nt < 4; nt++)
#pragma unroll
            for (int r = 0; r < 4; r++) Dc[mt][nt][r] = 0.0f;

    for (int c = 0; c < 32; c++) {
        const uint32_t buf = sb + (c & 1) * 49152;
        const uint32_t nbuf = sb + ((c + 1) & 1) * 49152;
        const int kcn = (c + 1) * 64;

        // issue V cp.async for c+1 + prefetch P (it=0,1) before the MMA wall
        float4 pf[4];
        if (c + 1 < 32) {
            k2_stageB(nbuf, tid, vb0 + kcn);
#pragma unroll
            for (int it = 0; it < 2; it++) {
                size_t off = (size_t)(q0 + sq[it]) * N_ + kcn + sg[it] * 8;
                pf[it * 2]     = *(const float4*)(Pb + off);
                pf[it * 2 + 1] = *(const float4*)(Pb + off + 4);
            }
        }

        mma_phase(buf, Dc, arow, brow, acol);

        if (c + 1 < 32) {
            // stage A for chunk c+1 into nbuf (writes to nbuf are safe:
            // MMA reads of nbuf only start after the next __syncthreads)
            uint32_t bofs = ((c + 1) & 1) * 49152u;
#pragma unroll
            for (int it = 0; it < 4; it++) {
                size_t off = (size_t)(q0 + sq[it]) * N_ + kcn + sg[it] * 8;
                float4 p0, p1;
                if (it < 2) { p0 = pf[it * 2]; p1 = pf[it * 2 + 1]; }
                else {
                    p0 = *(const float4*)(Pb + off);
                    p1 = *(const float4*)(Pb + off + 4);
                }
                float4 r0 = *(const float4*)(g_rdenom + off);
                float4 r1 = *(const float4*)(g_rdenom + off + 4);
                uint32_t h[4], l[4];
                split2(p0.x * r0.x, p0.y * r0.y, h[0], l[0]);
                split2(p0.z * r0.z, p0.w * r0.w, h[1], l[1]);
                split2(p1.x * r1.x, p1.y * r1.y, h[2], l[2]);
                split2(p1.z * r1.z, p1.w * r1.w, h[3], l[3]);
                uint32_t dsw = SW128((uint32_t)(sq[it] * 128 + sg[it] * 16));
                *(uint4*)(smem + bofs + dsw)         = make_uint4(h[0], h[1], h[2], h[3]);
                *(uint4*)(smem + bofs + dsw + 16384) = make_uint4(l[0], l[1], l[2], l[3]);
            }
            asm volatile("cp.async.wait_group 0;" ::: "memory");
        }
        __syncthreads();
    }

    // ---- epilogue: write O ----
#pragma unroll
    for (int mt = 0; mt < 2; mt++) {
        int r0 = q0 + wq * 32 + mt * 16 + (lane >> 2);
#pragma unroll
        for (int nt = 0; nt < 4; nt++) {
            int cc = wd * 32 + nt * 8 + 2 * (lane & 3);
            *(float2*)(O + ((size_t)b * N_ + r0) * D_ + cc) =
                make_float2(Dc[mt][nt][0], Dc[mt][nt][1]);
            *(float2*)(O + ((size_t)b * N_ + r0 + 8) * D_ + cc) =
                make_float2(Dc[mt][nt][2], Dc[mt][nt][3]);
        }
    }
}

// ===========================================================================
extern "C" void kernel_launch(void* const* d_in, const int* in_sizes, int n_in,
                              void* d_out, int out_size) {
    const float* Q = (const float*)d_in[0];
    const float* K = (const float*)d_in[1];
    const float* V = (const float*)d_in[2];
    float* O = (float*)d_out;

    cudaFuncSetAttribute(k1_scores, cudaFuncAttributeMaxDynamicSharedMemorySize, 98304);
    cudaFuncSetAttribute(k2_out, cudaFuncAttributeMaxDynamicSharedMemorySize, 98304);

    const int n8 = (int)((size_t)B_ * ND / 8);
    k0_split<<<n8 / 256, 256>>>(Q, 0, 0.125f);
    k0_split<<<n8 / 256, 256>>>(K, 1, 1.0f);
    k0_vt<<<dim3(N_ / 64, B_), 256>>>(V);

    k1_scores<<<dim3(N_ / 64, N_ / 128), 256, 98304>>>();
    k2_out<<<dim3(B_, N_ / 128), 256, 98304>>>(O);
}

// round 9
// speedup vs baseline: 3.0577x; 1.0593x over previous
#include <cuda_runtime.h>
#include <cuda_bf16.h>
#include <cstdint>
#include <cstddef>

constexpr int B_ = 16, N_ = 2048, D_ = 64;
constexpr size_t ND = (size_t)N_ * D_;
constexpr size_t N2 = (size_t)N_ * N_;
// fragment-tiled P: tile (qt,kt) = 128q x 64k = 8192 floats, laid out in k1
// fragment order: idx = w*1024 + (mt*4+nt)*128 + lane*4 + e
//   q = qt*128 + (w>>1)*32 + mt*16 + (lane>>2) + (e>=2 ? 8 : 0)
//   k = kt*64  + (w&1)*32  + nt*8  + 2*(lane&3) + (e&1)
constexpr int TILE = 8192;

// ---- scratch (__device__ globals; no allocations allowed) ----
__device__ float g_P[(size_t)B_ * N2];        // fragment-tiled exp(scores)
__device__ float g_rdenom[N2];                // fragment-tiled (no b)
__device__ __nv_bfloat16 g_Qh[(size_t)B_ * ND];
__device__ __nv_bfloat16 g_Ql[(size_t)B_ * ND];
__device__ __nv_bfloat16 g_Kh[(size_t)B_ * ND];
__device__ __nv_bfloat16 g_Kl[(size_t)B_ * ND];
__device__ __nv_bfloat16 g_Vth[(size_t)B_ * ND];  // [b][d][k]
__device__ __nv_bfloat16 g_Vtl[(size_t)B_ * ND];

#define SW128(o) ((o) ^ (((o) >> 3) & 0x70))

__device__ __forceinline__ uint32_t smem_u32(const void* p) {
    uint32_t a;
    asm("{ .reg .u64 t; cvta.to.shared.u64 t, %1; cvt.u32.u64 %0, t; }" : "=r"(a) : "l"(p));
    return a;
}
__device__ __forceinline__ void ldmx4(uint32_t* r, uint32_t addr) {
    asm volatile("ldmatrix.sync.aligned.m8n8.x4.shared.b16 {%0,%1,%2,%3}, [%4];"
                 : "=r"(r[0]), "=r"(r[1]), "=r"(r[2]), "=r"(r[3]) : "r"(addr));
}
__device__ __forceinline__ void mma16816(float* d, const uint32_t* a, uint32_t b0, uint32_t b1) {
    asm volatile(
        "mma.sync.aligned.m16n8k16.row.col.f32.bf16.bf16.f32 "
        "{%0,%1,%2,%3}, {%4,%5,%6,%7}, {%8,%9}, {%0,%1,%2,%3};"
        : "+f"(d[0]), "+f"(d[1]), "+f"(d[2]), "+f"(d[3])
        : "r"(a[0]), "r"(a[1]), "r"(a[2]), "r"(a[3]), "r"(b0), "r"(b1));
}
__device__ __forceinline__ void split2(float a, float b, uint32_t& h, uint32_t& l) {
    __nv_bfloat16 ha = __float2bfloat16(a), hb = __float2bfloat16(b);
    float la = a - __bfloat162float(ha), lb = b - __bfloat162float(hb);
    __nv_bfloat16 lae = __float2bfloat16(la), lbe = __float2bfloat16(lb);
    h = (uint32_t)__bfloat16_as_ushort(ha) | ((uint32_t)__bfloat16_as_ushort(hb) << 16);
    l = (uint32_t)__bfloat16_as_ushort(lae) | ((uint32_t)__bfloat16_as_ushort(lbe) << 16);
}
__device__ __forceinline__ void cp16(uint32_t dst, const void* src) {
    asm volatile("cp.async.cg.shared.global [%0], [%1], 16;" :: "r"(dst), "l"(src));
}
__device__ __forceinline__ void cp_commit() {
    asm volatile("cp.async.commit_group;" ::: "memory");
}

// ===========================================================================
// k0a: split Q/K (fp32 -> bf16 hi/lo); scale folded into Q
// ===========================================================================
__global__ __launch_bounds__(256) void k0_split(const float* __restrict__ in, int sel, float scale) {
    __nv_bfloat16* hi = sel ? g_Kh : g_Qh;
    __nv_bfloat16* lo = sel ? g_Kl : g_Ql;
    size_t i = (size_t)blockIdx.x * blockDim.x + threadIdx.x;
    if (i >= (size_t)B_ * ND / 8) return;
    float4 a = ((const float4*)in)[i * 2];
    float4 b = ((const float4*)in)[i * 2 + 1];
    uint32_t h[4], l[4];
    split2(a.x * scale, a.y * scale, h[0], l[0]);
    split2(a.z * scale, a.w * scale, h[1], l[1]);
    split2(b.x * scale, b.y * scale, h[2], l[2]);
    split2(b.z * scale, b.w * scale, h[3], l[3]);
    ((uint4*)hi)[i] = make_uint4(h[0], h[1], h[2], h[3]);
    ((uint4*)lo)[i] = make_uint4(l[0], l[1], l[2], l[3]);
}

// ===========================================================================
// k0b: transpose V [b][k][d] -> Vt [b][d][k], bf16 hi/lo split
// ===========================================================================
__global__ __launch_bounds__(256) void k0_vt(const float* __restrict__ V) {
    __shared__ float smv[64][65];
    const int b = blockIdx.y, k0 = blockIdx.x * 64;
    const int t = threadIdx.x;
    const float* Vb = V + ((size_t)b * N_ + k0) * D_;
#pragma unroll
    for (int it = 0; it < 4; it++) {
        int f = t + it * 256;
        int k = f >> 4, d4 = f & 15;
        float4 v = *(const float4*)(Vb + k * D_ + d4 * 4);
        smv[k][d4 * 4 + 0] = v.x;
        smv[k][d4 * 4 + 1] = v.y;
        smv[k][d4 * 4 + 2] = v.z;
        smv[k][d4 * 4 + 3] = v.w;
    }
    __syncthreads();
    const int d = t >> 2, kg = t & 3;
    uint32_t h[8], l[8];
#pragma unroll
    for (int j = 0; j < 8; j++)
        split2(smv[kg * 16 + j * 2][d], smv[kg * 16 + j * 2 + 1][d], h[j], l[j]);
    size_t off = ((size_t)b * D_ + d) * N_ + k0 + kg * 16;
    *(uint4*)(g_Vth + off)     = make_uint4(h[0], h[1], h[2], h[3]);
    *(uint4*)(g_Vth + off + 8) = make_uint4(h[4], h[5], h[6], h[7]);
    *(uint4*)(g_Vtl + off)     = make_uint4(l[0], l[1], l[2], l[3]);
    *(uint4*)(g_Vtl + off + 8) = make_uint4(l[4], l[5], l[6], l[7]);
}

// ---------------------------------------------------------------------------
// Shared-fragment 3-split MMA phase for k1.
// Buffer: Ah@+0 (16K), Al@+16384, Bh@+32768 (8K), Bl@+40960
// ---------------------------------------------------------------------------
__device__ __forceinline__ void mma_phase(uint32_t buf, float Dc[2][4][4],
                                          int arow, int brow, int acol) {
#pragma unroll
    for (int ks = 0; ks < 4; ks++) {
        uint32_t aH[2][4], bH[2][4];
#pragma unroll
        for (int mt = 0; mt < 2; mt++)
            ldmx4(aH[mt], buf + SW128((uint32_t)((arow + mt * 16) * 128 + ks * 32 + acol)));
#pragma unroll
        for (int np = 0; np < 2; np++)
            ldmx4(bH[np], buf + 32768 + SW128((uint32_t)((brow + np * 16) * 128 + ks * 32 + acol)));
#pragma unroll
        for (int mt = 0; mt < 2; mt++)
#pragma unroll
            for (int np = 0; np < 2; np++) {
                mma16816(Dc[mt][np * 2],     aH[mt], bH[np][0], bH[np][2]);
                mma16816(Dc[mt][np * 2 + 1], aH[mt], bH[np][1], bH[np][3]);
            }
        {   // Al * Bh
            uint32_t aL[2][4];
#pragma unroll
            for (int mt = 0; mt < 2; mt++)
                ldmx4(aL[mt], buf + 16384 + SW128((uint32_t)((arow + mt * 16) * 128 + ks * 32 + acol)));
#pragma unroll
            for (int mt = 0; mt < 2; mt++)
#pragma unroll
                for (int np = 0; np < 2; np++) {
                    mma16816(Dc[mt][np * 2],     aL[mt], bH[np][0], bH[np][2]);
                    mma16816(Dc[mt][np * 2 + 1], aL[mt], bH[np][1], bH[np][3]);
                }
        }
        {   // Ah * Bl
            uint32_t bL[2][4];
#pragma unroll
            for (int np = 0; np < 2; np++)
                ldmx4(bL[np], buf + 40960 + SW128((uint32_t)((brow + np * 16) * 128 + ks * 32 + acol)));
#pragma unroll
            for (int mt = 0; mt < 2; mt++)
#pragma unroll
                for (int np = 0; np < 2; np++) {
                    mma16816(Dc[mt][np * 2],     aH[mt], bL[np][0], bL[np][2]);
                    mma16816(Dc[mt][np * 2 + 1], aH[mt], bL[np][1], bL[np][3]);
                }
        }
    }
}

// ===========================================================================
// k1: scores. Double-buffered cp.async staging; P/rdenom stored in
// fragment-tiled layout -> 8 coalesced STG.128 per thread per b.
// ===========================================================================
__device__ __forceinline__ void k1_stage(uint32_t buf, int tid, size_t qbase, size_t kbase) {
#pragma unroll
    for (int it = 0; it < 4; it++) {
        int u = tid + it * 256;
        int q = u >> 3, g = u & 7;
        uint32_t dst = buf + SW128((uint32_t)(q * 128 + g * 16));
        cp16(dst,         g_Qh + qbase + q * D_ + g * 8);
        cp16(dst + 16384, g_Ql + qbase + q * D_ + g * 8);
    }
#pragma unroll
    for (int it = 0; it < 2; it++) {
        int u = tid + it * 256;
        int k = u >> 3, g = u & 7;
        uint32_t dst = buf + 32768 + SW128((uint32_t)(k * 128 + g * 16));
        cp16(dst,        g_Kh + kbase + k * D_ + g * 8);
        cp16(dst + 8192, g_Kl + kbase + k * D_ + g * 8);
    }
    cp_commit();
}

__global__ __launch_bounds__(256, 2) void k1_scores() {
    extern __shared__ __align__(128) uint8_t smem[];   // 98304
    const uint32_t sb = smem_u32(smem);
    const int tid = threadIdx.x;
    const int lane = tid & 31, w = tid >> 5;
    const int kt = blockIdx.x, qt = blockIdx.y;
    const int q0 = qt * 128, k0 = kt * 64;
    const int wq = w >> 1, wk = w & 1;
    const int arow = wq * 32 + (lane & 15);
    const int brow = wk * 32 + (lane & 15);
    const int acol = (lane >> 4) * 16;
    const int fragoff = w * 1024 + lane * 4;   // per-thread slot in tile

    float denom[2][4][4];
#pragma unroll
    for (int mt = 0; mt < 2; mt++)
#pragma unroll
        for (int nt = 0; nt < 4; nt++)
#pragma unroll
            for (int r = 0; r < 4; r++) denom[mt][nt][r] = 0.0f;

    k1_stage(sb,         tid, (size_t)0 * ND + (size_t)q0 * D_, (size_t)0 * ND + (size_t)k0 * D_);
    k1_stage(sb + 49152, tid, (size_t)1 * ND + (size_t)q0 * D_, (size_t)1 * ND + (size_t)k0 * D_);

    for (int b = 0; b < B_; b++) {
        const uint32_t buf = sb + (b & 1) * 49152;
        if (b < B_ - 1) asm volatile("cp.async.wait_group 1;" ::: "memory");
        else            asm volatile("cp.async.wait_group 0;" ::: "memory");
        __syncthreads();

        float Dc[2][4][4];
#pragma unroll
        for (int mt = 0; mt < 2; mt++)
#pragma unroll
            for (int nt = 0; nt < 4; nt++)
#pragma unroll
                for (int r = 0; r < 4; r++) Dc[mt][nt][r] = 0.0f;

        mma_phase(buf, Dc, arow, brow, acol);

        // ---- exp + denom + fragment-tiled coalesced P store ----
        float* Pb = g_P + (((size_t)b * 16 + qt) * 32 + kt) * TILE + fragoff;
#pragma unroll
        for (int mt = 0; mt < 2; mt++)
#pragma unroll
            for (int nt = 0; nt < 4; nt++) {
                float e0 = __expf(Dc[mt][nt][0]);
                float e1 = __expf(Dc[mt][nt][1]);
                float e2 = __expf(Dc[mt][nt][2]);
                float e3 = __expf(Dc[mt][nt][3]);
                denom[mt][nt][0] += e0; denom[mt][nt][1] += e1;
                denom[mt][nt][2] += e2; denom[mt][nt][3] += e3;
                *(float4*)(Pb + (mt * 4 + nt) * 128) = make_float4(e0, e1, e2, e3);
            }
        __syncthreads();
        if (b + 2 < B_)
            k1_stage(buf, tid, (size_t)(b + 2) * ND + (size_t)q0 * D_,
                               (size_t)(b + 2) * ND + (size_t)k0 * D_);
    }

    // ---- rdenom (fragment-tiled, coalesced) ----
    float* Rb = g_rdenom + ((size_t)qt * 32 + kt) * TILE + fragoff;
#pragma unroll
    for (int mt = 0; mt < 2; mt++)
#pragma unroll
        for (int nt = 0; nt < 4; nt++)
            *(float4*)(Rb + (mt * 4 + nt) * 128) = make_float4(
                1.0f / denom[mt][nt][0], 1.0f / denom[mt][nt][1],
                1.0f / denom[mt][nt][2], 1.0f / denom[mt][nt][3]);
}

// ===========================================================================
// k2: out[b] = (P[b]*rdenom) @ V[b]. Block (b, qt), 256 thr.
// Warp w: wq2 = w>>1 (32 q rows), kh = w&1 (k-half of each 64-chunk) —
// matches k1's warp roles, so A-fragments load straight from g_P/g_rdenom
// with coalesced LDG.128 into mma registers. NO smem/ldmatrix for A.
// V double-buffered via cp.async (8KB hi + 8KB lo per chunk).
// Final cross-warp (kh) reduction through smem, then O store.
// ===========================================================================
__device__ __forceinline__ void k2_stageB(uint32_t buf, int tid, size_t vbase) {
#pragma unroll
    for (int it = 0; it < 2; it++) {
        int u = tid + it * 256;
        int d = u >> 3, g = u & 7;
        uint32_t dst = buf + SW128((uint32_t)(d * 128 + g * 16));
        cp16(dst,        g_Vth + vbase + (size_t)d * N_ + g * 8);
        cp16(dst + 8192, g_Vtl + vbase + (size_t)d * N_ + g * 8);
    }
    cp_commit();
}

__global__ __launch_bounds__(256, 2) void k2_out(float* __restrict__ O) {
    extern __shared__ __align__(128) uint8_t smem[];   // 32768
    const uint32_t sb = smem_u32(smem);
    const int tid = threadIdx.x;
    const int lane = tid & 31, w = tid >> 5;
    const int b = blockIdx.x, qt = blockIdx.y;
    const int wq2 = w >> 1, kh = w & 1;
    const int fragoff = w * 1024 + lane * 4;
    const size_t vb0 = (size_t)b * ND;

    float Dc[2][8][4];
#pragma unroll
    for (int mt = 0; mt < 2; mt++)
#pragma unroll
        for (int j = 0; j < 8; j++)
#pragma unroll
            for (int r = 0; r < 4; r++) Dc[mt][j][r] = 0.0f;

    k2_stageB(sb, tid, vb0);   // chunk 0 -> buffer 0

    for (int c = 0; c < 32; c++) {
        const uint32_t buf = sb + (c & 1) * 16384;
        if (c + 1 < 32) {
            k2_stageB(sb + ((c + 1) & 1) * 16384, tid, vb0 + (c + 1) * 64);
            asm volatile("cp.async.wait_group 1;" ::: "memory");
        } else {
            asm volatile("cp.async.wait_group 0;" ::: "memory");
        }
        __syncthreads();

        const float* pA = g_P + (((size_t)b * 16 + qt) * 32 + c) * TILE + fragoff;
        const float* pR = g_rdenom + ((size_t)qt * 32 + c) * TILE + fragoff;

#pragma unroll
        for (int kg = 0; kg < 2; kg++) {
            // A fragments: normalized P, hi/lo split, direct to registers
            uint32_t aH[2][4], aL[2][4];
#pragma unroll
            for (int mt = 0; mt < 2; mt++)
#pragma unroll
                for (int hf = 0; hf < 2; hf++) {
                    int i = mt * 4 + kg * 2 + hf;
                    float4 p = *(const float4*)(pA + i * 128);
                    float4 r = *(const float4*)(pR + i * 128);
                    uint32_t h01, l01, h23, l23;
                    split2(p.x * r.x, p.y * r.y, h01, l01);
                    split2(p.z * r.z, p.w * r.w, h23, l23);
                    aH[mt][hf * 2] = h01; aH[mt][hf * 2 + 1] = h23;
                    aL[mt][hf * 2] = l01; aL[mt][hf * 2 + 1] = l23;
                }
#pragma unroll
            for (int g16 = 0; g16 < 4; g16++) {
                uint32_t bh[4], bl[4];
                uint32_t boff = SW128((uint32_t)((g16 * 16 + (lane & 15)) * 128 +
                                                 kh * 64 + kg * 32 + (lane >> 4) * 16));
                ldmx4(bh, buf + boff);
                ldmx4(bl, buf + 8192 + boff);
#pragma unroll
                for (int mt = 0; mt < 2; mt++) {
                    mma16816(Dc[mt][g16 * 2],     aH[mt], bh[0], bh[2]);
                    mma16816(Dc[mt][g16 * 2 + 1], aH[mt], bh[1], bh[3]);
                    mma16816(Dc[mt][g16 * 2],     aL[mt], bh[0], bh[2]);
                    mma16816(Dc[mt][g16 * 2 + 1], aL[mt], bh[1], bh[3]);
                    mma16816(Dc[mt][g16 * 2],     aH[mt], bl[0], bl[2]);
                    mma16816(Dc[mt][g16 * 2 + 1], aH[mt], bl[1], bl[3]);
                }
            }
        }
        __syncthreads();   // all ldmx done before buf is re-staged
    }

    // ---- cross-warp (kh) reduction via smem, then O store ----
    if (kh == 1) {
#pragma unroll
        for (int mt = 0; mt < 2; mt++)
#pragma unroll
            for (int j = 0; j < 8; j++)
                *(float4*)(smem + wq2 * 8192 + (mt * 8 + j) * 512 + lane * 16) =
                    make_float4(Dc[mt][j][0], Dc[mt][j][1], Dc[mt][j][2], Dc[mt][j][3]);
    }
    __syncthreads();
    if (kh == 0) {
#pragma unroll
        for (int mt = 0; mt < 2; mt++) {
            int r0 = qt * 128 + wq2 * 32 + mt * 16 + (lane >> 2);
#pragma unroll
            for (int j = 0; j < 8; j++) {
                float4 o = *(float4*)(smem + wq2 * 8192 + (mt * 8 + j) * 512 + lane * 16);
                float v0 = Dc[mt][j][0] + o.x;
                float v1 = Dc[mt][j][1] + o.y;
                float v2 = Dc[mt][j][2] + o.z;
                float v3 = Dc[mt][j][3] + o.w;
                int cc = j * 8 + 2 * (lane & 3);
                *(float2*)(O + ((size_t)b * N_ + r0) * D_ + cc)     = make_float2(v0, v1);
                *(float2*)(O + ((size_t)b * N_ + r0 + 8) * D_ + cc) = make_float2(v2, v3);
            }
        }
    }
}

// ===========================================================================
extern "C" void kernel_launch(void* const* d_in, const int* in_sizes, int n_in,
                              void* d_out, int out_size) {
    const float* Q = (const float*)d_in[0];
    const float* K = (const float*)d_in[1];
    const float* V = (const float*)d_in[2];
    float* O = (float*)d_out;

    cudaFuncSetAttribute(k1_scores, cudaFuncAttributeMaxDynamicSharedMemorySize, 98304);
    cudaFuncSetAttribute(k2_out, cudaFuncAttributeMaxDynamicSharedMemorySize, 32768);

    const int n8 = (int)((size_t)B_ * ND / 8);
    k0_split<<<n8 / 256, 256>>>(Q, 0, 0.125f);
    k0_split<<<n8 / 256, 256>>>(K, 1, 1.0f);
    k0_vt<<<dim3(N_ / 64, B_), 256>>>(V);

    k1_scores<<<dim3(N_ / 64, N_ / 128), 256, 98304>>>();   // (kt, qt)
    k2_out<<<dim3(B_, N_ / 128), 256, 32768>>>(O);          // (b, qt)
}